// round 14
// baseline (speedup 1.0000x reference)
#include <cuda_runtime.h>
#include <cuda_fp16.h>
#include <cstdint>

// ======================= problem constants =======================
#define DIMX     64
#define HIDX     256
#define NSTEPS   32
#define NTHREADS 256

// two-size grid: 444 big CTAs (256 rows, m32/warp) ~ 3 waves,
// then 136 small CTAs (128 rows, m16/warp) backfill the tail.
#define NBIG     444
#define NSMALL   136
#define BIGROWS  (NBIG * 256)

// ======================= SMEM layout (bytes) =====================
#define SM_B1P  0
#define SM_TW1P 512
#define SM_B2P  1024
#define SM_DB3  3072
#define SM_W1   4096
#define SM_W2   36864
#define SM_W3   167936
#define SMEM_BYTES 200704

#define SWZ(off) ((off) ^ (((off) >> 3) & 0x70))

// ======================= device helpers ==========================
__device__ __forceinline__ uint32_t smem_to_u32(const void* p) {
    uint32_t a;
    asm("{ .reg .u64 t; cvta.to.shared.u64 t, %1; cvt.u32.u64 %0, t; }" : "=r"(a) : "l"(p));
    return a;
}
__device__ __forceinline__ uint32_t pack_f16x2(float lo, float hi) {
    uint32_t r;
    asm("cvt.rn.f16x2.f32 %0, %1, %2;" : "=r"(r) : "f"(hi), "f"(lo));
    return r;
}
__device__ __forceinline__ uint32_t silu2h(uint32_t ah, uint32_t h05) {
    uint32_t t, s, h;
    asm("mul.rn.f16x2 %0, %1, %2;"     : "=r"(t) : "r"(ah), "r"(h05));
    asm("tanh.approx.f16x2 %0, %1;"    : "=r"(t) : "r"(t));
    asm("fma.rn.f16x2 %0, %1, %2, %2;" : "=r"(s) : "r"(t), "r"(h05));
    asm("mul.rn.f16x2 %0, %1, %2;"     : "=r"(h) : "r"(ah), "r"(s));
    return h;
}
__device__ __forceinline__ uint32_t hfma2(uint32_t a, uint32_t b, uint32_t c) {
    uint32_t r;
    asm("fma.rn.f16x2 %0, %1, %2, %3;" : "=r"(r) : "r"(a), "r"(b), "r"(c));
    return r;
}
__device__ __forceinline__ void ldsm4(uint32_t& r0, uint32_t& r1, uint32_t& r2, uint32_t& r3,
                                      uint32_t addr) {
    asm volatile("ldmatrix.sync.aligned.m8n8.x4.shared.b16 {%0,%1,%2,%3}, [%4];"
                 : "=r"(r0), "=r"(r1), "=r"(r2), "=r"(r3) : "r"(addr));
}
__device__ __forceinline__ void mma_h(uint32_t* d, const uint32_t* a, uint32_t b0, uint32_t b1) {
    asm volatile("mma.sync.aligned.m16n8k16.row.col.f16.f16.f16.f16 "
                 "{%0,%1}, {%2,%3,%4,%5}, {%6,%7}, {%0,%1};"
                 : "+r"(d[0]), "+r"(d[1])
                 : "r"(a[0]), "r"(a[1]), "r"(a[2]), "r"(a[3]), "r"(b0), "r"(b1));
}
__device__ __forceinline__ void mma_f(float* c, const uint32_t* a, uint32_t b0, uint32_t b1) {
    asm volatile("mma.sync.aligned.m16n8k16.row.col.f32.f16.f16.f32 "
                 "{%0,%1,%2,%3}, {%4,%5,%6,%7}, {%8,%9}, {%0,%1,%2,%3};"
                 : "+f"(c[0]), "+f"(c[1]), "+f"(c[2]), "+f"(c[3])
                 : "r"(a[0]), "r"(a[1]), "r"(a[2]), "r"(a[3]), "r"(b0), "r"(b1));
}

// ======================= templated per-CTA body ===================
template <int MT>
__device__ __forceinline__ void flow_body(
    long rowStart, const float* __restrict__ x0, float* __restrict__ out,
    uint32_t sbase, const uint32_t* sb1p, const uint32_t* stw1p,
    const uint32_t* sb2p, const float* sdb3)
{
    const int tid  = threadIdx.x;
    const int wid  = tid >> 5;
    const int lane = tid & 31;
    const int r = lane & 7, g = lane >> 3;
    const uint32_t ld_row = (uint32_t)((r + ((g >> 1) << 3)) * 128);
    const uint32_t g1 = (uint32_t)(g & 1);
    #define KOFF(kt) ((((uint32_t)(((kt) << 1) | g1) ^ (uint32_t)r) << 4))

    const float dt = 1.0f / NSTEPS;
    const uint32_t h05 = 0x38003800u;
    const long rowBase = rowStart + wid * (MT * 16) + (lane >> 2);
    const int  q2 = (lane & 3) * 2;
    const int  l4 = lane & 3;

    float x[MT * 32];
    #pragma unroll
    for (int mt = 0; mt < MT; mt++) {
        const float* pA = x0 + (rowBase + mt * 16) * DIMX;
        const float* pB = x0 + (rowBase + mt * 16 + 8) * DIMX;
        #pragma unroll
        for (int nt = 0; nt < 8; nt++) {
            float2 a = *(const float2*)(pA + nt * 8 + q2);
            float2 b = *(const float2*)(pB + nt * 8 + q2);
            x[(mt * 8 + nt) * 4 + 0] = a.x; x[(mt * 8 + nt) * 4 + 1] = a.y;
            x[(mt * 8 + nt) * 4 + 2] = b.x; x[(mt * 8 + nt) * 4 + 3] = b.y;
        }
    }

    uint32_t hA[MT * 64];   // GEMM1 accum -> (after fused silu) GEMM2 A frags

    // silu one k-slice (MT*4 words) of hA in place
    #define SILU_SLICE(kt) do { \
        _Pragma("unroll") for (int mt = 0; mt < MT; mt++) { \
            uint32_t* h = hA + ((kt) * MT + mt) * 4; \
            h[0] = silu2h(h[0], h05); h[1] = silu2h(h[1], h05); \
            h[2] = silu2h(h[2], h05); h[3] = silu2h(h[3], h05); } } while (0)

    #define G2_INIT(ch, C2) do { \
        _Pragma("unroll") for (int nt = 0; nt < 4; nt++) { \
            const uint32_t b2v = sb2p[(ch) * 16 + nt * 4 + l4]; \
            _Pragma("unroll") for (int mt = 0; mt < MT; mt++) { \
                (C2)[(nt * MT + mt) * 2 + 0] = b2v; \
                (C2)[(nt * MT + mt) * 2 + 1] = b2v; } } } while (0)

    // FUSE_SILU: chunk 0 applies silu to hA slice kt+1 while slice kt's mmas issue.
    #define G2_MMA(ch, C2, FUSE_SILU) do { \
        const uint32_t w2base = sbase + SM_W2 + (uint32_t)((ch) * 4096) + ld_row; \
        uint32_t B0[4], B1[4]; \
        ldsm4(B0[0], B0[1], B0[2], B0[3], w2base + KOFF(0)); \
        ldsm4(B1[0], B1[1], B1[2], B1[3], w2base + 2048u + KOFF(0)); \
        _Pragma("unroll") for (int kt = 0; kt < 16; kt++) { \
            uint32_t N0[4], N1[4]; \
            if (kt < 15) { \
                const int kn = kt + 1; \
                const uint32_t ko = (uint32_t)((kn >> 2) * 32768) + KOFF(kn & 3); \
                ldsm4(N0[0], N0[1], N0[2], N0[3], w2base + ko); \
                ldsm4(N1[0], N1[1], N1[2], N1[3], w2base + 2048u + ko); } \
            if ((FUSE_SILU) && kt < 15) SILU_SLICE(kt + 1); \
            _Pragma("unroll") for (int mt = 0; mt < MT; mt++) { \
                const uint32_t* a = hA + (kt * MT + mt) * 4; \
                mma_h((C2) + (0 * MT + mt) * 2, a, B0[0], B0[1]); \
                mma_h((C2) + (1 * MT + mt) * 2, a, B0[2], B0[3]); \
                mma_h((C2) + (2 * MT + mt) * 2, a, B1[0], B1[1]); \
                mma_h((C2) + (3 * MT + mt) * 2, a, B1[2], B1[3]); } \
            if (kt < 15) { \
                _Pragma("unroll") for (int j = 0; j < 4; j++) { B0[j] = N0[j]; B1[j] = N1[j]; } } \
        } } while (0)

    // EPI_G3 with W3-fragment double-buffering: first ldsm hoisted above the
    // silu loop (latency rides under MUFU), each next fragment prefetched
    // before the current mma_f group.
    #define EPI_G3(ch, C2) do { \
        uint32_t Wc[4]; \
        { const uint32_t w3b0 = sbase + SM_W3 + (uint32_t)(((ch) * 2 >> 2) * 8192) + ld_row; \
          ldsm4(Wc[0], Wc[1], Wc[2], Wc[3], w3b0 + KOFF((ch) * 2 & 3)); } \
        _Pragma("unroll") for (int i = 0; i < MT * 8; i++) (C2)[i] = silu2h((C2)[i], h05); \
        _Pragma("unroll") for (int p = 0; p < 2; p++) { \
            uint32_t af[MT][4]; \
            _Pragma("unroll") for (int mt = 0; mt < MT; mt++) { \
                af[mt][0] = (C2)[((2 * p) * MT + mt) * 2 + 0]; \
                af[mt][1] = (C2)[((2 * p) * MT + mt) * 2 + 1]; \
                af[mt][2] = (C2)[((2 * p + 1) * MT + mt) * 2 + 0]; \
                af[mt][3] = (C2)[((2 * p + 1) * MT + mt) * 2 + 1]; } \
            const int kt3 = (ch) * 2 + p; \
            const uint32_t w3base = sbase + SM_W3 + (uint32_t)((kt3 >> 2) * 8192) + ld_row; \
            const uint32_t k3off = KOFF(kt3 & 3); \
            _Pragma("unroll") for (int ntp = 0; ntp < 4; ntp++) { \
                uint32_t Wn[4]; \
                if (ntp < 3) { \
                    ldsm4(Wn[0], Wn[1], Wn[2], Wn[3], \
                          w3base + (uint32_t)((ntp + 1) * 2048) + k3off); \
                } else if (p == 0) { \
                    const int kt3n = (ch) * 2 + 1; \
                    ldsm4(Wn[0], Wn[1], Wn[2], Wn[3], \
                          sbase + SM_W3 + (uint32_t)((kt3n >> 2) * 8192) + ld_row + KOFF(kt3n & 3)); \
                } \
                _Pragma("unroll") for (int mt = 0; mt < MT; mt++) { \
                    mma_f(x + (mt * 8 + 2 * ntp) * 4,     af[mt], Wc[0], Wc[1]); \
                    mma_f(x + (mt * 8 + 2 * ntp + 1) * 4, af[mt], Wc[2], Wc[3]); } \
                if (ntp < 3 || p == 0) { \
                    Wc[0] = Wn[0]; Wc[1] = Wn[1]; Wc[2] = Wn[2]; Wc[3] = Wn[3]; } \
            } } } while (0)

    #pragma unroll 1
    for (int s = 0; s < NSTEPS; s++) {
        const float tvalf = ((float)s + 0.5f) * dt;
        const uint32_t tval2 = pack_f16x2(tvalf, tvalf);

        // ======== GEMM1 (k-outer, f16 accum in hA, B-fragment prefetch) ========
        #pragma unroll
        for (int pair = 0; pair < 16; pair++) {
            const uint32_t biasA = hfma2(tval2, stw1p[pair * 8 + l4],     sb1p[pair * 8 + l4]);
            const uint32_t biasB = hfma2(tval2, stw1p[pair * 8 + 4 + l4], sb1p[pair * 8 + 4 + l4]);
            #pragma unroll
            for (int mt = 0; mt < MT; mt++) {
                uint32_t* h = hA + (pair * MT + mt) * 4;
                h[0] = biasA; h[1] = biasA; h[2] = biasB; h[3] = biasB;
            }
        }
        #pragma unroll
        for (int kt = 0; kt < 4; kt++) {
            uint32_t xk[MT * 4];
            #pragma unroll
            for (int mt = 0; mt < MT; mt++) {
                const float* xs = x + (mt * 8 + 2 * kt) * 4;
                xk[mt * 4 + 0] = pack_f16x2(xs[0], xs[1]);
                xk[mt * 4 + 1] = pack_f16x2(xs[2], xs[3]);
                xk[mt * 4 + 2] = pack_f16x2(xs[4], xs[5]);
                xk[mt * 4 + 3] = pack_f16x2(xs[6], xs[7]);
            }
            const uint32_t koff = KOFF(kt);
            const uint32_t w1base = sbase + SM_W1 + ld_row + koff;
            uint32_t Wc0, Wc1, Wc2, Wc3;
            ldsm4(Wc0, Wc1, Wc2, Wc3, w1base);
            #pragma unroll
            for (int pair = 0; pair < 16; pair++) {
                uint32_t Wn0, Wn1, Wn2, Wn3;
                if (pair < 15)
                    ldsm4(Wn0, Wn1, Wn2, Wn3, w1base + (uint32_t)((pair + 1) * 2048));
                #pragma unroll
                for (int mt = 0; mt < MT; mt++) {
                    mma_h(hA + (pair * MT + mt) * 4 + 0, xk + mt * 4, Wc0, Wc1);
                    mma_h(hA + (pair * MT + mt) * 4 + 2, xk + mt * 4, Wc2, Wc3);
                }
                if (pair < 15) { Wc0 = Wn0; Wc1 = Wn1; Wc2 = Wn2; Wc3 = Wn3; }
            }
        }

        // ==== GEMM2+GEMM3, chunk pipeline; hA silu fused into chunk 0 ====
        {
            uint32_t C2a[MT * 8], C2b[MT * 8];
            SILU_SLICE(0);
            G2_INIT(0, C2a); G2_MMA(0, C2a, 1);
            #pragma unroll
            for (int ch = 0; ch < 8; ch += 2) {
                G2_INIT(ch + 1, C2b); G2_MMA(ch + 1, C2b, 0);
                EPI_G3(ch, C2a);
                if (ch < 6) { G2_INIT(ch + 2, C2a); G2_MMA(ch + 2, C2a, 0); }
                EPI_G3(ch + 1, C2b);
            }
        }

        // ---- x += dt * b3 ----
        #pragma unroll
        for (int nt = 0; nt < 8; nt++) {
            float2 p = *(const float2*)(sdb3 + nt * 8 + q2);
            #pragma unroll
            for (int mt = 0; mt < MT; mt++) {
                float* xs = x + (mt * 8 + nt) * 4;
                xs[0] += p.x; xs[1] += p.y; xs[2] += p.x; xs[3] += p.y;
            }
        }
    }

    // ---- store result ----
    #pragma unroll
    for (int mt = 0; mt < MT; mt++) {
        float* pA = out + (rowBase + mt * 16) * DIMX;
        float* pB = out + (rowBase + mt * 16 + 8) * DIMX;
        #pragma unroll
        for (int nt = 0; nt < 8; nt++) {
            const float* xs = x + (mt * 8 + nt) * 4;
            *(float2*)(pA + nt * 8 + q2) = make_float2(xs[0], xs[1]);
            *(float2*)(pB + nt * 8 + q2) = make_float2(xs[2], xs[3]);
        }
    }
    #undef KOFF
    #undef SILU_SLICE
    #undef G2_INIT
    #undef G2_MMA
    #undef EPI_G3
}

// ======================= kernel ==================================
__global__ void __launch_bounds__(NTHREADS, 1) flow_kernel(
    const float* __restrict__ x0, const float* __restrict__ W1,
    const float* __restrict__ b1, const float* __restrict__ W2,
    const float* __restrict__ b2, const float* __restrict__ W3,
    const float* __restrict__ b3, float* __restrict__ out)
{
    extern __shared__ char smem[];
    const uint32_t sbase = smem_to_u32(smem);
    const int tid = threadIdx.x;

    uint32_t* sb1p  = (uint32_t*)(smem + SM_B1P);
    uint32_t* stw1p = (uint32_t*)(smem + SM_TW1P);
    uint32_t* sb2p  = (uint32_t*)(smem + SM_B2P);
    float*    sdb3  = (float*)(smem + SM_DB3);

    const float dt = 1.0f / NSTEPS;

    if (tid < 128) {
        sb1p[tid]  = pack_f16x2(b1[2 * tid], b1[2 * tid + 1]);
        stw1p[tid] = pack_f16x2(W1[DIMX * HIDX + 2 * tid], W1[DIMX * HIDX + 2 * tid + 1]);
        sb2p[tid]  = pack_f16x2(b2[2 * tid], b2[2 * tid + 1]);
    }
    if (tid < DIMX) sdb3[tid] = dt * b3[tid];

    for (int idx = tid; idx < DIMX * HIDX; idx += NTHREADS) {          // W1 (64k,256n)
        int k = idx >> 8, n = idx & 255;
        uint32_t off = (uint32_t)(n * 128 + k * 2);
        *(__half*)(smem + SM_W1 + SWZ(off)) = __float2half(W1[idx]);
    }
    for (int idx = tid; idx < HIDX * HIDX; idx += NTHREADS) {          // W2 (256k,256n)
        int k = idx >> 8, n = idx & 255;
        int c = k >> 6, kk = k & 63;
        uint32_t off = (uint32_t)(n * 128 + kk * 2);
        *(__half*)(smem + SM_W2 + c * 32768 + SWZ(off)) = __float2half(W2[idx]);
    }
    for (int idx = tid; idx < HIDX * DIMX; idx += NTHREADS) {          // W3 (256k,64n), x dt
        int k = idx >> 6, n = idx & 63;
        int c = k >> 6, kk = k & 63;
        uint32_t off = (uint32_t)(n * 128 + kk * 2);
        *(__half*)(smem + SM_W3 + c * 8192 + SWZ(off)) = __float2half(dt * W3[idx]);
    }
    __syncthreads();

    if (blockIdx.x < NBIG) {
        flow_body<2>((long)blockIdx.x * 256, x0, out, sbase, sb1p, stw1p, sb2p, sdb3);
    } else {
        flow_body<1>((long)BIGROWS + (long)(blockIdx.x - NBIG) * 128,
                     x0, out, sbase, sb1p, stw1p, sb2p, sdb3);
    }
}

// ======================= launch ==================================
extern "C" void kernel_launch(void* const* d_in, const int* in_sizes, int n_in,
                              void* d_out, int out_size) {
    const float* x0 = (const float*)d_in[0];
    const float* W1 = (const float*)d_in[1];
    const float* b1 = (const float*)d_in[2];
    const float* W2 = (const float*)d_in[3];
    const float* b2 = (const float*)d_in[4];
    const float* W3 = (const float*)d_in[5];
    const float* b3 = (const float*)d_in[6];
    float* out = (float*)d_out;

    cudaFuncSetAttribute(flow_kernel, cudaFuncAttributeMaxDynamicSharedMemorySize, SMEM_BYTES);
    flow_kernel<<<NBIG + NSMALL, NTHREADS, SMEM_BYTES>>>(x0, W1, b1, W2, b2, W3, b3, out);
}

// round 15
// speedup vs baseline: 1.0321x; 1.0321x over previous
#include <cuda_runtime.h>
#include <cuda_fp16.h>
#include <cstdint>

// ======================= problem constants =======================
#define DIMX     64
#define HIDX     256
#define NSTEPS   32
#define NTHREADS 384          // 12 warps -> 3 warps per SMSP

// two-size grid: 592 big CTAs (192 rows, 12 warps x m16) = 4 exact waves,
// then 136 small CTAs (128 rows, 8 active warps) backfill the tail.
// 592*192 + 136*128 = 131072.
#define NBIG     592
#define NSMALL   136
#define BIGROWS  (NBIG * 192)

// ======================= SMEM layout (bytes) =====================
#define SM_B1P  0
#define SM_TW1P 512
#define SM_B2P  1024
#define SM_DB3  3072
#define SM_W1   4096
#define SM_W2   36864
#define SM_W3   167936
#define SMEM_BYTES 200704

#define SWZ(off) ((off) ^ (((off) >> 3) & 0x70))

// ======================= device helpers ==========================
__device__ __forceinline__ uint32_t smem_to_u32(const void* p) {
    uint32_t a;
    asm("{ .reg .u64 t; cvta.to.shared.u64 t, %1; cvt.u32.u64 %0, t; }" : "=r"(a) : "l"(p));
    return a;
}
__device__ __forceinline__ uint32_t pack_f16x2(float lo, float hi) {
    uint32_t r;
    asm("cvt.rn.f16x2.f32 %0, %1, %2;" : "=r"(r) : "f"(hi), "f"(lo));
    return r;
}
__device__ __forceinline__ uint32_t silu2h(uint32_t ah, uint32_t h05) {
    uint32_t t, s, h;
    asm("mul.rn.f16x2 %0, %1, %2;"     : "=r"(t) : "r"(ah), "r"(h05));
    asm("tanh.approx.f16x2 %0, %1;"    : "=r"(t) : "r"(t));
    asm("fma.rn.f16x2 %0, %1, %2, %2;" : "=r"(s) : "r"(t), "r"(h05));
    asm("mul.rn.f16x2 %0, %1, %2;"     : "=r"(h) : "r"(ah), "r"(s));
    return h;
}
__device__ __forceinline__ uint32_t hfma2(uint32_t a, uint32_t b, uint32_t c) {
    uint32_t r;
    asm("fma.rn.f16x2 %0, %1, %2, %3;" : "=r"(r) : "r"(a), "r"(b), "r"(c));
    return r;
}
__device__ __forceinline__ void ldsm4(uint32_t& r0, uint32_t& r1, uint32_t& r2, uint32_t& r3,
                                      uint32_t addr) {
    asm volatile("ldmatrix.sync.aligned.m8n8.x4.shared.b16 {%0,%1,%2,%3}, [%4];"
                 : "=r"(r0), "=r"(r1), "=r"(r2), "=r"(r3) : "r"(addr));
}
__device__ __forceinline__ void mma_h(uint32_t* d, const uint32_t* a, uint32_t b0, uint32_t b1) {
    asm volatile("mma.sync.aligned.m16n8k16.row.col.f16.f16.f16.f16 "
                 "{%0,%1}, {%2,%3,%4,%5}, {%6,%7}, {%0,%1};"
                 : "+r"(d[0]), "+r"(d[1])
                 : "r"(a[0]), "r"(a[1]), "r"(a[2]), "r"(a[3]), "r"(b0), "r"(b1));
}
__device__ __forceinline__ void mma_f(float* c, const uint32_t* a, uint32_t b0, uint32_t b1) {
    asm volatile("mma.sync.aligned.m16n8k16.row.col.f32.f16.f16.f32 "
                 "{%0,%1,%2,%3}, {%4,%5,%6,%7}, {%8,%9}, {%0,%1,%2,%3};"
                 : "+f"(c[0]), "+f"(c[1]), "+f"(c[2]), "+f"(c[3])
                 : "r"(a[0]), "r"(a[1]), "r"(a[2]), "r"(a[3]), "r"(b0), "r"(b1));
}

// ======================= per-warp body (m16) ======================
__device__ __forceinline__ void flow_body(
    long rowBaseWarp, const float* __restrict__ x0, float* __restrict__ out,
    uint32_t sbase, const uint32_t* sb1p, const uint32_t* stw1p,
    const uint32_t* sb2p, const float* sdb3, int lane)
{
    const int r = lane & 7, g = lane >> 3;
    const uint32_t ld_row = (uint32_t)((r + ((g >> 1) << 3)) * 128);
    const uint32_t g1 = (uint32_t)(g & 1);
    #define KOFF(kt) ((((uint32_t)(((kt) << 1) | g1) ^ (uint32_t)r) << 4))

    const float dt = 1.0f / NSTEPS;
    const uint32_t h05 = 0x38003800u;
    const long rowA = rowBaseWarp + (lane >> 2);
    const long rowB = rowA + 8;
    const int  q2 = (lane & 3) * 2;
    const int  l4 = lane & 3;

    float x[32];
    #pragma unroll
    for (int nt = 0; nt < 8; nt++) {
        float2 a = *(const float2*)(x0 + rowA * DIMX + nt * 8 + q2);
        float2 b = *(const float2*)(x0 + rowB * DIMX + nt * 8 + q2);
        x[nt * 4 + 0] = a.x; x[nt * 4 + 1] = a.y;
        x[nt * 4 + 2] = b.x; x[nt * 4 + 3] = b.y;
    }

    uint32_t hA[64];   // GEMM1 accum -> (after fused silu) GEMM2 A frags

    #define SILU_SLICE(kt) do { \
        uint32_t* h = hA + (kt) * 4; \
        h[0] = silu2h(h[0], h05); h[1] = silu2h(h[1], h05); \
        h[2] = silu2h(h[2], h05); h[3] = silu2h(h[3], h05); } while (0)

    #define G2_INIT(ch, C2) do { \
        _Pragma("unroll") for (int nt = 0; nt < 4; nt++) { \
            const uint32_t b2v = sb2p[(ch) * 16 + nt * 4 + l4]; \
            (C2)[nt * 2 + 0] = b2v; (C2)[nt * 2 + 1] = b2v; } } while (0)

    #define G2_MMA(ch, C2, FUSE_SILU) do { \
        const uint32_t w2base = sbase + SM_W2 + (uint32_t)((ch) * 4096) + ld_row; \
        uint32_t B0[4], B1[4]; \
        ldsm4(B0[0], B0[1], B0[2], B0[3], w2base + KOFF(0)); \
        ldsm4(B1[0], B1[1], B1[2], B1[3], w2base + 2048u + KOFF(0)); \
        _Pragma("unroll") for (int kt = 0; kt < 16; kt++) { \
            uint32_t N0[4], N1[4]; \
            if (kt < 15) { \
                const int kn = kt + 1; \
                const uint32_t ko = (uint32_t)((kn >> 2) * 32768) + KOFF(kn & 3); \
                ldsm4(N0[0], N0[1], N0[2], N0[3], w2base + ko); \
                ldsm4(N1[0], N1[1], N1[2], N1[3], w2base + 2048u + ko); } \
            if ((FUSE_SILU) && kt < 15) SILU_SLICE(kt + 1); \
            const uint32_t* a = hA + kt * 4; \
            mma_h((C2) + 0, a, B0[0], B0[1]); \
            mma_h((C2) + 2, a, B0[2], B0[3]); \
            mma_h((C2) + 4, a, B1[0], B1[1]); \
            mma_h((C2) + 6, a, B1[2], B1[3]); \
            if (kt < 15) { \
                _Pragma("unroll") for (int j = 0; j < 4; j++) { B0[j] = N0[j]; B1[j] = N1[j]; } } \
        } } while (0)

    #define EPI_G3(ch, C2) do { \
        _Pragma("unroll") for (int i = 0; i < 8; i++) (C2)[i] = silu2h((C2)[i], h05); \
        _Pragma("unroll") for (int p = 0; p < 2; p++) { \
            uint32_t af[4]; \
            af[0] = (C2)[(2 * p) * 2 + 0]; \
            af[1] = (C2)[(2 * p) * 2 + 1]; \
            af[2] = (C2)[(2 * p + 1) * 2 + 0]; \
            af[3] = (C2)[(2 * p + 1) * 2 + 1]; \
            const int kt3 = (ch) * 2 + p; \
            const uint32_t w3base = sbase + SM_W3 + (uint32_t)((kt3 >> 2) * 8192) + ld_row; \
            const uint32_t k3off = KOFF(kt3 & 3); \
            _Pragma("unroll") for (int ntp = 0; ntp < 4; ntp++) { \
                uint32_t w0, w1_, w2_, w3_; \
                ldsm4(w0, w1_, w2_, w3_, w3base + (uint32_t)(ntp * 2048) + k3off); \
                mma_f(x + (2 * ntp) * 4,     af, w0,  w1_); \
                mma_f(x + (2 * ntp + 1) * 4, af, w2_, w3_); } } } while (0)

    #pragma unroll 1
    for (int s = 0; s < NSTEPS; s++) {
        const float tvalf = ((float)s + 0.5f) * dt;
        const uint32_t tval2 = pack_f16x2(tvalf, tvalf);

        // ======== GEMM1 (k-outer, f16 accum in hA) ========
        #pragma unroll
        for (int pair = 0; pair < 16; pair++) {
            const uint32_t biasA = hfma2(tval2, stw1p[pair * 8 + l4],     sb1p[pair * 8 + l4]);
            const uint32_t biasB = hfma2(tval2, stw1p[pair * 8 + 4 + l4], sb1p[pair * 8 + 4 + l4]);
            uint32_t* h = hA + pair * 4;
            h[0] = biasA; h[1] = biasA; h[2] = biasB; h[3] = biasB;
        }
        #pragma unroll
        for (int kt = 0; kt < 4; kt++) {
            uint32_t xk[4];
            {
                const float* xs = x + 2 * kt * 4;
                xk[0] = pack_f16x2(xs[0], xs[1]);
                xk[1] = pack_f16x2(xs[2], xs[3]);
                xk[2] = pack_f16x2(xs[4], xs[5]);
                xk[3] = pack_f16x2(xs[6], xs[7]);
            }
            const uint32_t koff = KOFF(kt);
            #pragma unroll
            for (int pair = 0; pair < 16; pair++) {
                uint32_t w0, w1_, w2_, w3_;
                ldsm4(w0, w1_, w2_, w3_,
                      sbase + SM_W1 + (uint32_t)(pair * 2048) + ld_row + koff);
                mma_h(hA + pair * 4 + 0, xk, w0,  w1_);
                mma_h(hA + pair * 4 + 2, xk, w2_, w3_);
            }
        }

        // ==== GEMM2+GEMM3, chunk pipeline; hA silu fused into chunk 0 ====
        {
            uint32_t C2a[8], C2b[8];
            SILU_SLICE(0);
            G2_INIT(0, C2a); G2_MMA(0, C2a, 1);
            #pragma unroll
            for (int ch = 0; ch < 8; ch += 2) {
                G2_INIT(ch + 1, C2b); G2_MMA(ch + 1, C2b, 0);
                EPI_G3(ch, C2a);
                if (ch < 6) { G2_INIT(ch + 2, C2a); G2_MMA(ch + 2, C2a, 0); }
                EPI_G3(ch + 1, C2b);
            }
        }

        // ---- x += dt * b3 ----
        #pragma unroll
        for (int nt = 0; nt < 8; nt++) {
            float2 p = *(const float2*)(sdb3 + nt * 8 + q2);
            float* xs = x + nt * 4;
            xs[0] += p.x; xs[1] += p.y; xs[2] += p.x; xs[3] += p.y;
        }
    }

    // ---- store result ----
    #pragma unroll
    for (int nt = 0; nt < 8; nt++) {
        const float* xs = x + nt * 4;
        *(float2*)(out + rowA * DIMX + nt * 8 + q2) = make_float2(xs[0], xs[1]);
        *(float2*)(out + rowB * DIMX + nt * 8 + q2) = make_float2(xs[2], xs[3]);
    }
    #undef KOFF
    #undef SILU_SLICE
    #undef G2_INIT
    #undef G2_MMA
    #undef EPI_G3
}

// ======================= kernel ==================================
__global__ void __launch_bounds__(NTHREADS, 1) flow_kernel(
    const float* __restrict__ x0, const float* __restrict__ W1,
    const float* __restrict__ b1, const float* __restrict__ W2,
    const float* __restrict__ b2, const float* __restrict__ W3,
    const float* __restrict__ b3, float* __restrict__ out)
{
    extern __shared__ char smem[];
    const uint32_t sbase = smem_to_u32(smem);
    const int tid = threadIdx.x;
    const int wid = tid >> 5;
    const int lane = tid & 31;

    uint32_t* sb1p  = (uint32_t*)(smem + SM_B1P);
    uint32_t* stw1p = (uint32_t*)(smem + SM_TW1P);
    uint32_t* sb2p  = (uint32_t*)(smem + SM_B2P);
    float*    sdb3  = (float*)(smem + SM_DB3);

    const float dt = 1.0f / NSTEPS;

    if (tid < 128) {
        sb1p[tid]  = pack_f16x2(b1[2 * tid], b1[2 * tid + 1]);
        stw1p[tid] = pack_f16x2(W1[DIMX * HIDX + 2 * tid], W1[DIMX * HIDX + 2 * tid + 1]);
        sb2p[tid]  = pack_f16x2(b2[2 * tid], b2[2 * tid + 1]);
    }
    if (tid < DIMX) sdb3[tid] = dt * b3[tid];

    for (int idx = tid; idx < DIMX * HIDX; idx += NTHREADS) {          // W1 (64k,256n)
        int k = idx >> 8, n = idx & 255;
        uint32_t off = (uint32_t)(n * 128 + k * 2);
        *(__half*)(smem + SM_W1 + SWZ(off)) = __float2half(W1[idx]);
    }
    for (int idx = tid; idx < HIDX * HIDX; idx += NTHREADS) {          // W2 (256k,256n)
        int k = idx >> 8, n = idx & 255;
        int c = k >> 6, kk = k & 63;
        uint32_t off = (uint32_t)(n * 128 + kk * 2);
        *(__half*)(smem + SM_W2 + c * 32768 + SWZ(off)) = __float2half(W2[idx]);
    }
    for (int idx = tid; idx < HIDX * DIMX; idx += NTHREADS) {          // W3 (256k,64n), x dt
        int k = idx >> 6, n = idx & 63;
        int c = k >> 6, kk = k & 63;
        uint32_t off = (uint32_t)(n * 128 + kk * 2);
        *(__half*)(smem + SM_W3 + c * 8192 + SWZ(off)) = __float2half(dt * W3[idx]);
    }
    __syncthreads();

    if (blockIdx.x < NBIG) {
        // big CTA: 12 warps x 16 rows = 192 rows
        flow_body((long)blockIdx.x * 192 + wid * 16, x0, out,
                  sbase, sb1p, stw1p, sb2p, sdb3, lane);
    } else {
        // small CTA: 8 warps x 16 rows = 128 rows; warps 8-11 exit
        if (wid >= 8) return;
        flow_body((long)BIGROWS + (long)(blockIdx.x - NBIG) * 128 + wid * 16, x0, out,
                  sbase, sb1p, stw1p, sb2p, sdb3, lane);
    }
}

// ======================= launch ==================================
extern "C" void kernel_launch(void* const* d_in, const int* in_sizes, int n_in,
                              void* d_out, int out_size) {
    const float* x0 = (const float*)d_in[0];
    const float* W1 = (const float*)d_in[1];
    const float* b1 = (const float*)d_in[2];
    const float* W2 = (const float*)d_in[3];
    const float* b2 = (const float*)d_in[4];
    const float* W3 = (const float*)d_in[5];
    const float* b3 = (const float*)d_in[6];
    float* out = (float*)d_out;

    cudaFuncSetAttribute(flow_kernel, cudaFuncAttributeMaxDynamicSharedMemorySize, SMEM_BYTES);
    flow_kernel<<<NBIG + NSMALL, NTHREADS, SMEM_BYTES>>>(x0, W1, b1, W2, b2, W3, b3, out);
}